// round 2
// baseline (speedup 1.0000x reference)
#include <cuda_runtime.h>
#include <math.h>

// Problem constants
#define BB 4
#define CC 256
#define HH 64
#define WW 64
#define OO 256
#define HWV 4096
#define K2V 9

// Scratch (__device__ globals -- no allocation allowed)
__device__ float g_offp[4][18 * 16384];        // partial offset-conv sums (4 c-chunks)
__device__ float g_off[18 * 16384];            // offsets [b][18][h][w]
__device__ float g_wT[9 * 256 * 256];          // w_def transposed: [k2][c][o]
__device__ float g_raw[4 * 256 * 4096];        // pre-BN conv output [b][o][h][w]
__device__ float g_scale[256];
__device__ float g_shift[256];

// ---------------------------------------------------------------------------
// Kernel 0: transpose w_def [O][C][K2] -> g_wT [k2][c][o]
// ---------------------------------------------------------------------------
__global__ void k_transpose(const float* __restrict__ wdef) {
    int v = blockIdx.x * 256 + threadIdx.x;   // 589824 total
    if (v < 589824) {
        int k2 = v % 9;
        int c  = (v / 9) % 256;
        int o  = v / 2304;
        g_wT[(k2 * 256 + c) * 256 + o] = wdef[v];
    }
}

// ---------------------------------------------------------------------------
// Kernel 1: offset conv (18 out channels, 3x3, pad 1), split over 4 c-chunks
// grid: 256 blocks = 64 pixel-blocks x 4 c-chunks, 256 threads (1 px/thread)
// ---------------------------------------------------------------------------
__global__ void __launch_bounds__(256) k_offconv(const float* __restrict__ x,
                                                 const float* __restrict__ woff) {
    __shared__ float Wsh[18 * 64 * 9];   // 41472 B
    int pb    = blockIdx.x & 63;
    int chunk = blockIdx.x >> 6;
    int c0    = chunk * 64;

    for (int v = threadIdx.x; v < 18 * 576; v += 256) {
        int oc = v / 576;
        int rem = v % 576;            // cl*9 + tap, c contiguous in global too
        Wsh[v] = woff[oc * 2304 + c0 * 9 + rem];
    }
    __syncthreads();

    int pid = pb * 256 + threadIdx.x;  // 0..16383
    int b  = pid >> 12;
    int hw = pid & 4095;
    int h = hw >> 6, w = hw & 63;

    float acc[18];
#pragma unroll
    for (int i = 0; i < 18; i++) acc[i] = 0.f;

    const float* xb = x + (b * 256 + c0) * 4096;
    bool hv0 = (h > 0), hv2 = (h < 63), wv0 = (w > 0), wv2 = (w < 63);

    for (int cl = 0; cl < 64; cl++) {
        const float* xc = xb + cl * 4096;
        float xr[9];
#pragma unroll
        for (int dy = 0; dy < 3; dy++) {
            int hh = h + dy - 1;
            bool hv = (dy == 0) ? hv0 : ((dy == 2) ? hv2 : true);
#pragma unroll
            for (int dx = 0; dx < 3; dx++) {
                int ww = w + dx - 1;
                bool wv = (dx == 0) ? wv0 : ((dx == 2) ? wv2 : true);
                xr[dy * 3 + dx] = (hv && wv) ? xc[hh * 64 + ww] : 0.f;
            }
        }
        const float* wp = Wsh + cl * 9;
#pragma unroll
        for (int oc = 0; oc < 18; oc++) {
            const float* wo = wp + oc * 576;
            float s = acc[oc];
#pragma unroll
            for (int t = 0; t < 9; t++) s += xr[t] * wo[t];
            acc[oc] = s;
        }
    }
#pragma unroll
    for (int oc = 0; oc < 18; oc++)
        g_offp[chunk][(b * 18 + oc) * 4096 + hw] = acc[oc];
}

// Kernel 1b: combine 4 partials + bias
__global__ void k_offcomb(const float* __restrict__ boff) {
    int v = blockIdx.x * 256 + threadIdx.x;   // 294912
    if (v < 294912) {
        int oc = (v >> 12) % 18;
        g_off[v] = g_offp[0][v] + g_offp[1][v] + g_offp[2][v] + g_offp[3][v] + boff[oc];
    }
}

// ---------------------------------------------------------------------------
// Kernel 2: fused bilinear gather + main contraction (SGEMM-style)
// block = one (b, h) row: 64 pixels x 256 output channels, 256 threads,
// 8x8 register tile per thread. K = 9 (k2) x 256 (c) in chunks of 16 c.
// ---------------------------------------------------------------------------
__global__ void __launch_bounds__(256, 2) k_main(const float* __restrict__ x) {
    __shared__ __align__(16) float As[16][64];   // gathered vals [c_local][px]
    __shared__ __align__(16) float Ws[16][256];  // w_def tile   [c_local][o]
    __shared__ float sWt[4][64];      // 4 corner weights per pixel
    __shared__ int   sIx[4][64];      // 4 corner indices per pixel

    int b = blockIdx.x >> 6;
    int h = blockIdx.x & 63;
    int tid = threadIdx.x;
    int o0 = (tid & 31) * 8;          // lane -> o (LDS), warp-uniform px (broadcast)
    int p0 = (tid >> 5) * 8;

    float acc[8][8];
#pragma unroll
    for (int i = 0; i < 8; i++)
#pragma unroll
        for (int j = 0; j < 8; j++) acc[i][j] = 0.f;

    const float* xb = x + b * (256 * 4096);

    for (int k2 = 0; k2 < 9; k2++) {
        if (tid < 64) {
            int w = tid;
            float offy = g_off[(b * 18 + 2 * k2)     * 4096 + h * 64 + w];
            float offx = g_off[(b * 18 + 2 * k2 + 1) * 4096 + h * 64 + w];
            float py = offy + (float)(k2 / 3) + (float)h - 1.0f;
            float px = offx + (float)(k2 % 3) + (float)w - 1.0f;
            float y0f = floorf(py), x0f = floorf(px);
            float wy1 = py - y0f, wx1 = px - x0f;
            float wy0 = 1.f - wy1, wx0 = 1.f - wx1;
            bool vy0 = (y0f >= 0.f)       && (y0f <= 63.f);
            bool vy1 = (y0f + 1.f >= 0.f) && (y0f + 1.f <= 63.f);
            bool vx0 = (x0f >= 0.f)       && (x0f <= 63.f);
            bool vx1 = (x0f + 1.f >= 0.f) && (x0f + 1.f <= 63.f);
            int iy0 = min(max((int)y0f, 0), 63);
            int iy1 = min(max((int)y0f + 1, 0), 63);
            int ix0 = min(max((int)x0f, 0), 63);
            int ix1 = min(max((int)x0f + 1, 0), 63);
            sIx[0][w] = iy0 * 64 + ix0;  sWt[0][w] = (vy0 && vx0) ? wy0 * wx0 : 0.f;
            sIx[1][w] = iy0 * 64 + ix1;  sWt[1][w] = (vy0 && vx1) ? wy0 * wx1 : 0.f;
            sIx[2][w] = iy1 * 64 + ix0;  sWt[2][w] = (vy1 && vx0) ? wy1 * wx0 : 0.f;
            sIx[3][w] = iy1 * 64 + ix1;  sWt[3][w] = (vy1 && vx1) ? wy1 * wx1 : 0.f;
        }
        __syncthreads();

        const float* wTk = g_wT + k2 * 65536;
        for (int cc = 0; cc < 16; cc++) {
            int c0 = cc * 16;
            // Gather A tile: 16 c x 64 px, 4 values/thread, coalesced in px
#pragma unroll
            for (int i = 0; i < 4; i++) {
                int v = i * 256 + tid;
                int cl = v >> 6, p = v & 63;
                const float* xc = xb + (c0 + cl) * 4096;
                As[cl][p] = sWt[0][p] * xc[sIx[0][p]] + sWt[1][p] * xc[sIx[1][p]]
                          + sWt[2][p] * xc[sIx[2][p]] + sWt[3][p] * xc[sIx[3][p]];
            }
            // Load W tile: 16 c x 256 o, fully coalesced float4
            const float4* wsrc = (const float4*)(wTk + c0 * 256);
            float4* wdst = (float4*)&Ws[0][0];
#pragma unroll
            for (int i = 0; i < 4; i++) wdst[i * 256 + tid] = wsrc[i * 256 + tid];
            __syncthreads();

#pragma unroll
            for (int cl = 0; cl < 16; cl++) {
                float4 a0 = *(const float4*)&As[cl][p0];
                float4 a1 = *(const float4*)&As[cl][p0 + 4];
                float4 w0 = *(const float4*)&Ws[cl][o0];
                float4 w1 = *(const float4*)&Ws[cl][o0 + 4];
                float av[8] = {a0.x, a0.y, a0.z, a0.w, a1.x, a1.y, a1.z, a1.w};
                float wv[8] = {w0.x, w0.y, w0.z, w0.w, w1.x, w1.y, w1.z, w1.w};
#pragma unroll
                for (int i = 0; i < 8; i++)
#pragma unroll
                    for (int j = 0; j < 8; j++)
                        acc[i][j] += av[i] * wv[j];
            }
            __syncthreads();
        }
    }

    // Write: per o, 2 x float4 over consecutive w
    float* rb = g_raw + b * (256 * 4096) + h * 64;
#pragma unroll
    for (int j = 0; j < 8; j++) {
        float* ro = rb + (o0 + j) * 4096 + p0;
        float4 v0 = make_float4(acc[0][j], acc[1][j], acc[2][j], acc[3][j]);
        float4 v1 = make_float4(acc[4][j], acc[5][j], acc[6][j], acc[7][j]);
        *(float4*)ro = v0;
        *(float4*)(ro + 4) = v1;
    }
}

// ---------------------------------------------------------------------------
// Kernel 3: per-channel mean/var over (B,H,W), fold gamma/beta into scale/shift
// ---------------------------------------------------------------------------
__global__ void k_stats(const float* __restrict__ gamma, const float* __restrict__ beta) {
    int o = blockIdx.x;
    double s = 0.0, s2 = 0.0;
    for (int b = 0; b < 4; b++) {
        const float* p = g_raw + (b * 256 + o) * 4096;
        for (int i = threadIdx.x; i < 4096; i += 256) {
            float v = p[i];
            s += (double)v;
            s2 += (double)v * (double)v;
        }
    }
    __shared__ double sh[256], sh2[256];
    sh[threadIdx.x] = s;
    sh2[threadIdx.x] = s2;
    __syncthreads();
    for (int st = 128; st > 0; st >>= 1) {
        if (threadIdx.x < st) {
            sh[threadIdx.x]  += sh[threadIdx.x + st];
            sh2[threadIdx.x] += sh2[threadIdx.x + st];
        }
        __syncthreads();
    }
    if (threadIdx.x == 0) {
        double mean = sh[0] / 16384.0;
        double var  = sh2[0] / 16384.0 - mean * mean;
        float scale = gamma[o] * rsqrtf((float)var + 1e-5f);
        g_scale[o] = scale;
        g_shift[o] = beta[o] - (float)mean * scale;
    }
}

// ---------------------------------------------------------------------------
// Kernel 4: normalize + ReLU, vectorized.
// Total output = 4*256*4096 floats = 1,048,576 float4s  (R0 bug: was 4x over)
// ---------------------------------------------------------------------------
__global__ void k_norm(float* __restrict__ out) {
    int i4 = blockIdx.x * 256 + threadIdx.x;   // 1048576 float4s
    if (i4 < 1048576) {
        int o = (i4 >> 10) & 255;              // 1024 float4 per (b,o) plane
        float sc = g_scale[o], shf = g_shift[o];
        float4 v = ((const float4*)g_raw)[i4];
        v.x = fmaxf(v.x * sc + shf, 0.f);
        v.y = fmaxf(v.y * sc + shf, 0.f);
        v.z = fmaxf(v.z * sc + shf, 0.f);
        v.w = fmaxf(v.w * sc + shf, 0.f);
        ((float4*)out)[i4] = v;
    }
}

// ---------------------------------------------------------------------------
extern "C" void kernel_launch(void* const* d_in, const int* in_sizes, int n_in,
                              void* d_out, int out_size) {
    const float* x     = (const float*)d_in[0];
    const float* woff  = (const float*)d_in[1];
    const float* boff  = (const float*)d_in[2];
    const float* wdef  = (const float*)d_in[3];
    const float* gamma = (const float*)d_in[4];
    const float* beta  = (const float*)d_in[5];
    float* out = (float*)d_out;

    k_transpose<<<2304, 256>>>(wdef);
    k_offconv<<<256, 256>>>(x, woff);
    k_offcomb<<<1152, 256>>>(boff);
    k_main<<<256, 256>>>(x);
    k_stats<<<256, 256>>>(gamma, beta);
    k_norm<<<4096, 256>>>(out);
}